// round 9
// baseline (speedup 1.0000x reference)
#include <cuda_runtime.h>
#include <cuda_fp16.h>
#include <cstdint>

// Problem dims (fixed):
//  x: (2,1024,32,512) -> M = 65536 rows of K=512
//  QKV cols = 1536 (Q 0-511, K 512-1023, V 1024-1535), out proj N=512
#define M_TOTAL 65536

// ---------------- scratch (device globals; no runtime allocation) ----------
__device__ uint32_t g_Qh[(size_t)M_TOTAL * 256];    // roped+scaled Q, half2 along d
__device__ uint32_t g_Kh[(size_t)M_TOTAL * 256];    // roped K, half2 along d
__device__ uint32_t g_Vh[(size_t)M_TOTAL * 256];    // V, half2 along d
__device__ uint32_t g_Xp[(size_t)M_TOTAL * 256];    // x as half2 (k-contiguous)
__device__ uint32_t g_AOp[(size_t)M_TOTAL * 256];   // attn out as half2 (k-contiguous)
__device__ uint32_t g_WQKVp[512 * 768];             // [k][n2] half2 along n
__device__ uint32_t g_WOp[512 * 256];               // [k][n2] half2 along n
__device__ float    g_cos[1024];
__device__ float    g_sin[1024];
__device__ int      g_mask[2];

// ---------------- helpers ----------------------------------------------------
__device__ __forceinline__ uint32_t packh2(float lo, float hi) {
    __half2 h = __floats2half2_rn(lo, hi);
    return *reinterpret_cast<uint32_t*>(&h);
}
__device__ __forceinline__ float2 unpackh2(uint32_t w) {
    return __half22float2(*reinterpret_cast<__half2*>(&w));
}
__device__ __forceinline__ uint32_t smem_u32(const void* p) {
    uint32_t a;
    asm("{ .reg .u64 t; cvta.to.shared.u64 t, %1; cvt.u32.u64 %0, t; }"
        : "=r"(a) : "l"(p));
    return a;
}
__device__ __forceinline__ void cp16(uint32_t dst, const void* src) {
    asm volatile("cp.async.cg.shared.global [%0], [%1], 16;"
                 :: "r"(dst), "l"(src) : "memory");
}
__device__ __forceinline__ void cp_commit() {
    asm volatile("cp.async.commit_group;" ::: "memory");
}

// ---------------- setup: pack x/weights to fp16, rope table, mask -----------
__global__ void setup_kernel(
    const float* __restrict__ x,
    const float* __restrict__ w_q,
    const float* __restrict__ w_kv,
    const float* __restrict__ w_out,
    const float* __restrict__ inv_freq,
    const uint32_t* __restrict__ m)
{
    const int bid = blockIdx.x;
    if (bid < 16384) {
        size_t base = ((size_t)bid * 256 + threadIdx.x) * 4;
#pragma unroll
        for (int j = 0; j < 4; j++) {
            size_t w = base + j;
            float2 v = *(const float2*)(x + 2 * w);
            g_Xp[w] = packh2(v.x, v.y);
        }
    } else if (bid < 16384 + 512) {
        // weights, n-pair packed: qkv 512x768 words, out 512x256 words
        size_t base = ((size_t)(bid - 16384) * 256 + threadIdx.x) * 4;
#pragma unroll
        for (int j = 0; j < 4; j++) {
            size_t w = base + j;
            if (w < 393216) {
                int k = (int)(w / 768), n2 = (int)(w % 768);
                int n = 2 * n2;
                float a, b;
                if (n < 512) {
                    a = w_q[(size_t)k * 512 + n];
                    b = w_q[(size_t)k * 512 + n + 1];
                } else {
                    a = w_kv[(size_t)k * 1024 + n - 512];
                    b = w_kv[(size_t)k * 1024 + n - 511];
                }
                g_WQKVp[w] = packh2(a, b);
            } else {
                size_t w2 = w - 393216;
                int k = (int)(w2 / 256), n2 = (int)(w2 % 256);
                g_WOp[w2] = packh2(w_out[(size_t)k * 512 + 2 * n2],
                                   w_out[(size_t)k * 512 + 2 * n2 + 1]);
            }
        }
    } else {
#pragma unroll
        for (int j = 0; j < 4; j++) {
            int t = threadIdx.x * 4 + j;
            float ang = (float)(t >> 5) * inv_freq[t & 31];
            g_cos[t] = cosf(ang);
            g_sin[t] = sinf(ang);
        }
        if (threadIdx.x == 0) {
            uint32_t w0 = m[0], w1 = m[1];
            if (w0 <= 1u && w1 <= 1u) {
                g_mask[0] = (int)w0; g_mask[1] = (int)w1;
            } else {
                const unsigned char* p = (const unsigned char*)m;
                g_mask[0] = p[0] ? 1 : 0; g_mask[1] = p[1] ? 1 : 0;
            }
        }
    }
}

// Epilogue store for the fused QKV GEMM (c in [0,1536), even; v0,v1 = c,c+1).
__device__ __forceinline__ void epi_store(int r, int c, float v0, float v1) {
    int seg = c >> 9;
    int off = c & 511;
    size_t p = (size_t)r * 256 + (off >> 1);
    if (seg == 2) {
        g_Vh[p] = packh2(v0, v1);
    } else {
        int pos = r & 31;
        int fi = (c & 63) >> 1;
        float cs = g_cos[pos * 32 + fi];
        float sn = g_sin[pos * 32 + fi];
        if (seg == 0) { v0 *= 0.125f; v1 *= 0.125f; }
        uint32_t w = packh2(v0 * cs - v1 * sn, v1 * cs + v0 * sn);
        ((seg == 0) ? g_Qh : g_Kh)[p] = w;
    }
}

// ---------------- fp16 mma.sync GEMM, BK=64, 3-stage cp.async, full LDSM ----
// C[M,N] = A[M,512]*B[512,N]; block 128x128, BK=64 (4 k16 steps, 8 chunks),
// 8 warps (2x4), warp tile 64x32 of m16n8k16.
// A smem: half2 A[m][k2] k-contiguous, 32 words/row + pad -> stride 36 (LDSM CF)
// B smem: half2 B[k][n2] n-contiguous, 64 words/row + pad -> stride 68
//         (trans-LDSM phases: banks 4k mod 32, conflict-free)
#define AS_STRIDE 36
#define BS_STRIDE 68
#define AS_WORDS (128 * AS_STRIDE)   // 4608
#define BS_WORDS (64 * BS_STRIDE)    // 4352
#define STG_WORDS (AS_WORDS + BS_WORDS)          // 8960
#define GEMM_SMEM_BYTES (3 * STG_WORDS * 4)      // 107520

template <int FUSED>
__global__ __launch_bounds__(256, 2) void gemm_kernel(float* __restrict__ Cout)
{
    extern __shared__ uint32_t sw[];

    const uint32_t* const Apack = FUSED ? g_Xp : g_AOp;
    const uint32_t* const Bpack = FUSED ? g_WQKVp : g_WOp;

    const int tid = threadIdx.x;
    const int warp = tid >> 5, lane = tid & 31;
    const int wm = (warp >> 2) * 64, wn = (warp & 3) * 32;
    const int grp = lane >> 2, tig = lane & 3;
    const int rowBase = blockIdx.y * 128;
    const int bx = blockIdx.x;
    const int ldBpw = FUSED ? 768 : 256;   // B words per k-row
    const int nbw = bx * 64;               // n-offset in words
    const uint32_t sbase = smem_u32(sw);

    auto ISSUE = [&](int c, int s) {
        const uint32_t stg = sbase + (uint32_t)s * STG_WORDS * 4;
        // A: 1024 cp16 (128 rows x 32 words, 4/thread)
#pragma unroll
        for (int i = 0; i < 4; i++) {
            int op = tid + 256 * i;
            int row = op >> 3, c4 = (op & 7) * 4;
            cp16(stg + (uint32_t)(row * AS_STRIDE + c4) * 4,
                 Apack + (size_t)(rowBase + row) * 256 + c * 32 + c4);
        }
        // B: 1024 cp16 (64 k-rows x 64 words, 4/thread)
#pragma unroll
        for (int i = 0; i < 4; i++) {
            int op = tid + 256 * i;
            int r = op >> 4, n4 = (op & 15) * 4;
            cp16(stg + (uint32_t)(AS_WORDS + r * BS_STRIDE + n4) * 4,
                 Bpack + (size_t)(c * 64 + r) * ldBpw + nbw + n4);
        }
    };

    // A ldmatrix: lane -> row wm+mf*16+(lane&15), word k0w + (lane>>4)*4
    const int lrow = lane & 15, lcolA = (lane >> 4) << 2;
    // B trans ldmatrix: lane -> k-row k0h+(lane&15), n-col += (lane>>4)*8
    const int bcol8 = (lane >> 4) << 3;

    uint32_t af[4][4], bf[4][2];
    auto LOADFRAG = [&](int s, int ks) {
        const uint32_t aBase = sbase + (uint32_t)(s * STG_WORDS) * 4;
        const uint32_t bBase = aBase + (uint32_t)AS_WORDS * 4;
        const int k0w = ks * 8;      // A k-offset in words
        const int k0h = ks * 16;     // B k-offset in rows (halves of k)
#pragma unroll
        for (int mf = 0; mf < 4; mf++) {
            uint32_t addr = aBase +
                (uint32_t)((wm + mf * 16 + lrow) * AS_STRIDE + k0w + lcolA) * 4;
            asm volatile(
                "ldmatrix.sync.aligned.m8n8.x4.shared.b16 {%0,%1,%2,%3}, [%4];"
                : "=r"(af[mf][0]), "=r"(af[mf][1]), "=r"(af[mf][2]), "=r"(af[mf][3])
                : "r"(addr));
        }
#pragma unroll
        for (int nf2 = 0; nf2 < 2; nf2++) {
            int ncol = wn + nf2 * 16 + bcol8;                 // halves
            uint32_t addr = bBase +
                (uint32_t)((k0h + lrow) * BS_STRIDE + (ncol >> 1)) * 4;
            asm volatile(
                "ldmatrix.sync.aligned.m8n8.x4.trans.shared.b16 {%0,%1,%2,%3}, [%4];"
                : "=r"(bf[2 * nf2][0]), "=r"(bf[2 * nf2][1]),
                  "=r"(bf[2 * nf2 + 1][0]), "=r"(bf[2 * nf2 + 1][1])
                : "r"(addr));
        }
    };

    float acc[4][4][4];
#pragma unroll
    for (int a = 0; a < 4; a++)
#pragma unroll
        for (int b = 0; b < 4; b++)
#pragma unroll
            for (int c = 0; c < 4; c++) acc[a][b][c] = 0.0f;

    ISSUE(0, 0); cp_commit();
    ISSUE(1, 1); cp_commit();

#pragma unroll 1
    for (int c = 0; c < 8; c++) {
        const int s = c % 3;
        if (c < 7)
            asm volatile("cp.async.wait_group 1;" ::: "memory");
        else
            asm volatile("cp.async.wait_group 0;" ::: "memory");
        __syncthreads();   // chunk c resident; all warps done with stage (c+2)%3
        if (c < 6) { ISSUE(c + 2, (c + 2) % 3); cp_commit(); }
#pragma unroll
        for (int ks = 0; ks < 4; ks++) {
            LOADFRAG(s, ks);
#pragma unroll
            for (int mf = 0; mf < 4; mf++)
#pragma unroll
                for (int nf = 0; nf < 4; nf++) {
                    asm volatile(
                        "mma.sync.aligned.m16n8k16.row.col.f32.f16.f16.f32 "
                        "{%0,%1,%2,%3}, {%4,%5,%6,%7}, {%8,%9}, {%0,%1,%2,%3};\n"
                        : "+f"(acc[mf][nf][0]), "+f"(acc[mf][nf][1]),
                          "+f"(acc[mf][nf][2]), "+f"(acc[mf][nf][3])
                        : "r"(af[mf][0]), "r"(af[mf][1]),
                          "r"(af[mf][2]), "r"(af[mf][3]),
                          "r"(bf[nf][0]), "r"(bf[nf][1]));
                }
        }
    }

    // -------- epilogue --------
    const int cBase = bx * 128 + wn;
#pragma unroll
    for (int mf = 0; mf < 4; mf++) {
        int r = rowBase + wm + mf * 16 + grp;
#pragma unroll
        for (int nf = 0; nf < 4; nf++) {
            int c = cBase + nf * 8 + 2 * tig;
            if (FUSED) {
                epi_store(r,     c, acc[mf][nf][0], acc[mf][nf][1]);
                epi_store(r + 8, c, acc[mf][nf][2], acc[mf][nf][3]);
            } else {
                *(float2*)(Cout + (size_t)r * 512 + c) =
                    make_float2(acc[mf][nf][0], acc[mf][nf][1]);
                *(float2*)(Cout + (size_t)(r + 8) * 512 + c) =
                    make_float2(acc[mf][nf][2], acc[mf][nf][3]);
            }
        }
    }
}

// ---------------- attention: one block per (b,s,h) --------------------------
// Reads fp16 Q/K/V, fp32 smem compute, writes packed half2 to g_AOp.
__global__ __launch_bounds__(256) void attn_kernel(const float* __restrict__ pos_bias)
{
    const int blk = blockIdx.x;        // 16384 = 2*1024*8
    const int h = blk & 7;
    const int bs = blk >> 3;
    const int b = bs >> 10;
    const int r0 = bs * 32;
    const int tid = threadIdx.x;
    const int hw = h * 32;             // head offset in half2 words

    if (g_mask[b]) {
        // attn = I -> out = v exactly (same fp16 values pass through)
        int row = tid >> 3, w4 = (tid & 7) * 4;
        size_t p = (size_t)(r0 + row) * 256 + hw + w4;
        *(uint4*)&g_AOp[p] = *(const uint4*)&g_Vh[p];
        return;
    }

    __shared__ float sQ[32][68];
    __shared__ float sK[32][68];
    __shared__ float sV[32][72];
    __shared__ float sS[32][33];

    {
        int row = tid >> 3, w4 = (tid & 7) * 4;   // 4 half2 words = 8 floats
        size_t p = (size_t)(r0 + row) * 256 + hw + w4;
        uint4 qw = *(const uint4*)&g_Qh[p];
        uint4 kw = *(const uint4*)&g_Kh[p];
        uint4 vw = *(const uint4*)&g_Vh[p];
        int d = w4 * 2;
        uint32_t qa[4] = {qw.x, qw.y, qw.z, qw.w};
        uint32_t ka[4] = {kw.x, kw.y, kw.z, kw.w};
        uint32_t va[4] = {vw.x, vw.y, vw.z, vw.w};
#pragma unroll
        for (int j = 0; j < 4; j++) {
            float2 q = unpackh2(qa[j]);
            float2 k = unpackh2(ka[j]);
            float2 v = unpackh2(va[j]);
            sQ[row][d + 2 * j]     = q.x; sQ[row][d + 2 * j + 1] = q.y;
            sK[row][d + 2 * j]     = k.x; sK[row][d + 2 * j + 1] = k.y;
            sV[row][d + 2 * j]     = v.x; sV[row][d + 2 * j + 1] = v.y;
        }
    }
    __syncthreads();

    // sim[i][j] = q_i . k_j + pos_bias; thread -> (i = tid>>3, j = (tid&7)+8r)
    const int i = tid >> 3;
    const int jb = tid & 7;
    float s0 = 0.f, s1 = 0.f, s2 = 0.f, s3 = 0.f;
#pragma unroll
    for (int d4 = 0; d4 < 64; d4 += 4) {
        float4 q = *(const float4*)&sQ[i][d4];
        float4 k0 = *(const float4*)&sK[jb][d4];
        float4 k1 = *(const float4*)&sK[jb + 8][d4];
        float4 k2 = *(const float4*)&sK[jb + 16][d4];
        float4 k3 = *(const float4*)&sK[jb + 24][d4];
        s0 += q.x * k0.x + q.y * k0.y + q.z * k0.z + q.w * k0.w;
        s1 += q.x * k1.x + q.y * k1.y + q.z * k1.z + q.w * k1.w;
        s2 += q.x * k2.x + q.y * k2.y + q.z * k2.z + q.w * k2.w;
        s3 += q.x * k3.x + q.y * k3.y + q.z * k3.z + q.w * k3.w;
    }
    const float* pb = pos_bias + (size_t)h * 1024 + i * 32 + jb;
    sS[i][jb +  0] = s0 + pb[0];
    sS[i][jb +  8] = s1 + pb[8];
    sS[i][jb + 16] = s2 + pb[16];
    sS[i][jb + 24] = s3 + pb[24];
    __syncthreads();

    // softmax: warp w -> rows 4w..4w+3, one lane per column
    const int warp = tid >> 5, lane = tid & 31;
#pragma unroll
    for (int rr = 0; rr < 4; rr++) {
        int row = warp * 4 + rr;
        float v = sS[row][lane];
        float m = v;
#pragma unroll
        for (int o = 16; o > 0; o >>= 1) m = fmaxf(m, __shfl_xor_sync(0xffffffffu, m, o));
        float e = expf(v - m);
        float sum = e;
#pragma unroll
        for (int o = 16; o > 0; o >>= 1) sum += __shfl_xor_sync(0xffffffffu, sum, o);
        sS[row][lane] = e / sum;
    }
    __syncthreads();

    // out[i][d] = sum_j attn[i][j] * v[j][d]; thread -> (row i, 8 d's)
    const int db = (tid & 7) * 8;
    float4 o0 = make_float4(0.f, 0.f, 0.f, 0.f);
    float4 o1 = make_float4(0.f, 0.f, 0.f, 0.f);
#pragma unroll
    for (int j = 0; j < 32; j++) {
        float a = sS[i][j];
        float4 v0 = *(const float4*)&sV[j][db];
        float4 v1 = *(const float4*)&sV[j][db + 4];
        o0.x += a * v0.x; o0.y += a * v0.y; o0.z += a * v0.z; o0.w += a * v0.w;
        o1.x += a * v1.x; o1.y += a * v1.y; o1.z += a * v1.z; o1.w += a * v1.w;
    }
    uint4 w = make_uint4(packh2(o0.x, o0.y), packh2(o0.z, o0.w),
                         packh2(o1.x, o1.y), packh2(o1.z, o1.w));
    *(uint4*)&g_AOp[(size_t)(r0 + i) * 256 + hw + (db >> 1)] = w;
}

// ---------------- launch ------------------------------------------------------
// Inputs resolved by element count (robust to metadata ordering); w_q vs w_out
// (both 262144) disambiguated by position relative to w_kv.
extern "C" void kernel_launch(void* const* d_in, const int* in_sizes, int n_in,
                              void* d_out, int out_size)
{
    (void)out_size;
    int ix = -1, ipb = -1, ifoc = -1, ikv = -1, iif = -1;
    int i262[2] = {-1, -1}; int n262 = 0;
    for (int i = 0; i < n_in; i++) {
        switch (in_sizes[i]) {
            case 33554432: ix = i; break;
            case 8192:     ipb = i; break;
            case 2:        ifoc = i; break;
            case 524288:   ikv = i; break;
            case 32:       iif = i; break;
            case 262144:   if (n262 < 2) i262[n262++] = i; break;
            default: break;
        }
    }
    int iq, io;
    if (n262 == 2 && i262[0] < ikv) { iq = i262[0]; io = i262[1]; }
    else                            { io = i262[0]; iq = i262[1]; }

    const float* x        = (const float*)d_in[ix];
    const float* pos_bias = (const float*)d_in[ipb];
    const uint32_t* mask  = (const uint32_t*)d_in[ifoc];
    const float* w_q      = (const float*)d_in[iq];
    const float* w_kv     = (const float*)d_in[ikv];
    const float* w_out    = (const float*)d_in[io];
    const float* inv_freq = (const float*)d_in[iif];
    float* out = (float*)d_out;

    cudaFuncSetAttribute(gemm_kernel<1>, cudaFuncAttributeMaxDynamicSharedMemorySize, GEMM_SMEM_BYTES);
    cudaFuncSetAttribute(gemm_kernel<0>, cudaFuncAttributeMaxDynamicSharedMemorySize, GEMM_SMEM_BYTES);

    setup_kernel<<<16384 + 512 + 1, 256>>>(x, w_q, w_kv, w_out, inv_freq, mask);
    gemm_kernel<1><<<dim3(12, 512), 256, GEMM_SMEM_BYTES>>>(nullptr);
    attn_kernel<<<16384, 256>>>(pos_bias);
    gemm_kernel<0><<<dim3(4, 512), 256, GEMM_SMEM_BYTES>>>(out);
}